// round 11
// baseline (speedup 1.0000x reference)
#include <cuda_runtime.h>
#include <cuda_bf16.h>

#define E_EDGES 1000000
#define N_NODES 50000
#define DIM     64
#define MSG     256
#define TILE_M  64
#define NT      (E_EDGES / TILE_M)      // 15625, exact

// ---------------- device-global scratch (no allocations) -------------------
__device__ __align__(16) float g_Ps[N_NODES * MSG];   // x_s@W1[0:64] + c
__device__ __align__(16) float g_Pt[N_NODES * MSG];   // x_t@W1[64:128]
__device__ __align__(16) float g_c[MSG];
__device__ int g_idx64;

__device__ __align__(16) __nv_bfloat16 g_ea_hi[E_EDGES * DIM];
__device__ __align__(16) __nv_bfloat16 g_ea_lo[E_EDGES * DIM];
__device__ __align__(16) __nv_bfloat16 g_W1T_hi[MSG * DIM];   // [256 n][64 k]
__device__ __align__(16) __nv_bfloat16 g_W1T_lo[MSG * DIM];
__device__ __align__(16) __nv_bfloat16 g_W2T_hi[DIM * MSG];   // [64 n][256 k]
__device__ __align__(16) __nv_bfloat16 g_W2T_lo[DIM * MSG];

// ---------------- helpers ---------------------------------------------------
__device__ __forceinline__ float2 ffma2(float2 a, float2 b, float2 c) {
    float2 d;
    asm("fma.rn.f32x2 %0, %1, %2, %3;"
        : "=l"(reinterpret_cast<unsigned long long &>(d))
        : "l"(reinterpret_cast<unsigned long long &>(a)),
          "l"(reinterpret_cast<unsigned long long &>(b)),
          "l"(reinterpret_cast<unsigned long long &>(c)));
    return d;
}
__device__ __forceinline__ float lrelu(float v) { return v >= 0.0f ? v : 0.01f * v; }

// pack: hi halfword = bf16(hv), lo halfword = bf16(lv)
__device__ __forceinline__ unsigned bfpack(float hv, float lv) {
    unsigned r;
    asm("cvt.rn.bf16x2.f32 %0, %1, %2;" : "=r"(r) : "f"(hv), "f"(lv));
    return r;
}
__device__ __forceinline__ void cp16(unsigned sa, const void* g) {
    asm volatile("cp.async.ca.shared.global [%0], [%1], 16;" :: "r"(sa), "l"(g));
}
__device__ __forceinline__ void cp_commit()  { asm volatile("cp.async.commit_group;"); }
__device__ __forceinline__ void cp_wait_all(){ asm volatile("cp.async.wait_group 0;"); }

__device__ __forceinline__ void ldx4(unsigned* r, unsigned a) {
    asm volatile("ldmatrix.sync.aligned.m8n8.x4.shared.b16 {%0,%1,%2,%3}, [%4];"
                 : "=r"(r[0]), "=r"(r[1]), "=r"(r[2]), "=r"(r[3]) : "r"(a));
}
__device__ __forceinline__ void ldx2(unsigned* r, unsigned a) {
    asm volatile("ldmatrix.sync.aligned.m8n8.x2.shared.b16 {%0,%1}, [%2];"
                 : "=r"(r[0]), "=r"(r[1]) : "r"(a));
}
__device__ __forceinline__ void mma16816(float* c, const unsigned* a, const unsigned* b) {
    asm volatile("mma.sync.aligned.m16n8k16.row.col.f32.bf16.bf16.f32 "
                 "{%0,%1,%2,%3}, {%4,%5,%6,%7}, {%8,%9}, {%0,%1,%2,%3};"
                 : "+f"(c[0]), "+f"(c[1]), "+f"(c[2]), "+f"(c[3])
                 : "r"(a[0]), "r"(a[1]), "r"(a[2]), "r"(a[3]), "r"(b[0]), "r"(b[1]));
}

// ---------------- prologue kernels ------------------------------------------
__global__ void detect_idx_kernel(const unsigned* __restrict__ idx) {
    if (threadIdx.x == 0) {
        int is64 = 1;
        for (int i = 0; i < 64; i++)
            if (idx[2 * i + 1] != 0u) { is64 = 0; break; }
        g_idx64 = is64;
    }
}

__global__ void cvec_kernel(const float* __restrict__ W1, const float* __restrict__ b1,
                            const float* __restrict__ xu) {
    int j = threadIdx.x;
    float acc = b1[j];
#pragma unroll 8
    for (int k = 0; k < DIM; k++) acc = fmaf(xu[k], W1[(192 + k) * MSG + j], acc);
    g_c[j] = acc;
}

__global__ __launch_bounds__(256) void split_ea_kernel(const float* __restrict__ ea) {
    long long i = (long long)blockIdx.x * 256 + threadIdx.x;   // float4 id
    float4 x = reinterpret_cast<const float4*>(ea)[i];
    unsigned hp0 = bfpack(x.y, x.x), hp1 = bfpack(x.w, x.z);
    float h0 = __uint_as_float(hp0 << 16), h1 = __uint_as_float(hp0 & 0xffff0000u);
    float h2 = __uint_as_float(hp1 << 16), h3 = __uint_as_float(hp1 & 0xffff0000u);
    unsigned lp0 = bfpack(x.y - h1, x.x - h0), lp1 = bfpack(x.w - h3, x.z - h2);
    reinterpret_cast<uint2*>(g_ea_hi)[i] = make_uint2(hp0, hp1);
    reinterpret_cast<uint2*>(g_ea_lo)[i] = make_uint2(lp0, lp1);
}

__global__ void split_w_kernel(const float* __restrict__ W1, const float* __restrict__ W2) {
    int i = blockIdx.x * 256 + threadIdx.x;   // 0..16383
    {   // W1T[n][k] = W1[(128+k)*256+n]
        int n = i >> 6, k = i & 63;
        float x = W1[(128 + k) * MSG + n];
        __nv_bfloat16 h = __float2bfloat16(x);
        g_W1T_hi[i] = h;
        g_W1T_lo[i] = __float2bfloat16(x - __bfloat162float(h));
    }
    {   // W2T[n][k] = W2[k*64+n]
        int n = i >> 8, k = i & 255;
        float x = W2[k * DIM + n];
        __nv_bfloat16 h = __float2bfloat16(x);
        g_W2T_hi[i] = h;
        g_W2T_lo[i] = __float2bfloat16(x - __bfloat162float(h));
    }
}

// ---------------- node precompute (fp32; c folded into Ps) ------------------
__global__ __launch_bounds__(256, 1)
void node_pre_kernel(const float* __restrict__ X, const float* __restrict__ Wsub,
                     int which, int N) {
    extern __shared__ float sm[];
    float* sW = sm;
    float* sA = sm + 16384;
    float* P  = which ? g_Pt : g_Ps;

    int t = threadIdx.x;
    int row0 = blockIdx.x * 64;
#pragma unroll
    for (int i = 0; i < 16; i++) {
        int idx = t + i * 256;
        reinterpret_cast<float4*>(sW)[idx] = reinterpret_cast<const float4*>(Wsub)[idx];
    }
#pragma unroll
    for (int i = 0; i < 4; i++) {
        int f = t + i * 256;
        int r = f >> 4, q = f & 15;
        float4 v = make_float4(0.f, 0.f, 0.f, 0.f);
        if (row0 + r < N) v = reinterpret_cast<const float4*>(X)[(row0 + r) * 16 + q];
        *reinterpret_cast<float4*>(&sA[r * 68 + q * 4]) = v;
    }
    __syncthreads();

    int tx = t & 31, ty = t >> 5;
    float2 acc[8][4];
#pragma unroll
    for (int e = 0; e < 8; e++)
#pragma unroll
        for (int j = 0; j < 4; j++) acc[e][j] = make_float2(0.f, 0.f);

    for (int k4 = 0; k4 < 64; k4 += 4) {
        float4 a[8];
#pragma unroll
        for (int e = 0; e < 8; e++)
            a[e] = *reinterpret_cast<const float4*>(&sA[(ty * 8 + e) * 68 + k4]);
#pragma unroll
        for (int kk = 0; kk < 4; kk++) {
            float4 b0 = *reinterpret_cast<const float4*>(&sW[(k4 + kk) * 256 + tx * 4]);
            float4 b1 = *reinterpret_cast<const float4*>(&sW[(k4 + kk) * 256 + 128 + tx * 4]);
#pragma unroll
            for (int e = 0; e < 8; e++) {
                float av = (kk == 0) ? a[e].x : (kk == 1) ? a[e].y : (kk == 2) ? a[e].z : a[e].w;
                float2 ad = make_float2(av, av);
                acc[e][0] = ffma2(ad, make_float2(b0.x, b0.y), acc[e][0]);
                acc[e][1] = ffma2(ad, make_float2(b0.z, b0.w), acc[e][1]);
                acc[e][2] = ffma2(ad, make_float2(b1.x, b1.y), acc[e][2]);
                acc[e][3] = ffma2(ad, make_float2(b1.z, b1.w), acc[e][3]);
            }
        }
    }

    float4 c0 = make_float4(0.f, 0.f, 0.f, 0.f), c1 = c0;
    if (which == 0) {
        c0 = *reinterpret_cast<const float4*>(&g_c[tx * 4]);
        c1 = *reinterpret_cast<const float4*>(&g_c[128 + tx * 4]);
    }
#pragma unroll
    for (int e = 0; e < 8; e++) {
        int r = row0 + ty * 8 + e;
        if (r < N) {
            float4 o0 = make_float4(acc[e][0].x + c0.x, acc[e][0].y + c0.y,
                                    acc[e][1].x + c0.z, acc[e][1].y + c0.w);
            float4 o1 = make_float4(acc[e][2].x + c1.x, acc[e][2].y + c1.y,
                                    acc[e][3].x + c1.z, acc[e][3].y + c1.w);
            *reinterpret_cast<float4*>(&P[r * 256 + tx * 4])       = o0;
            *reinterpret_cast<float4*>(&P[r * 256 + 128 + tx * 4]) = o1;
        }
    }
}

// ---------------- HMMA edge kernel ------------------------------------------
// smem map (bytes). 16B-unit XOR swizzle: unit c -> c ^ (row & 7)
#define W1H_OFF 0          // 256 rows x 128B
#define W1L_OFF 32768
#define W2H_OFF 65536      // 64 rows x 512B
#define W2L_OFF 98304
#define H1H_OFF 131072     // 64 rows x 512B
#define H1L_OFF 163840
#define EAH_OFF 196608     // 64 rows x 128B
#define EAL_OFF 204800
#define B2_OFF  212992     // 64 f32
#define GM_OFF  213248     // 64 f32
#define SP_OFF  213504     // 64 rows x 2 halves f32 partial ssq
#define SMEM_EDGE 214016

__global__ __launch_bounds__(256, 1)
void edge_mma_kernel(const void* __restrict__ eidx, const float* __restrict__ b2,
                     const float* __restrict__ gamma, float* __restrict__ out) {
    extern __shared__ char smc[];
    unsigned sb = (unsigned)__cvta_generic_to_shared(smc);
    int t = threadIdx.x, wid = t >> 5, li = t & 31;

    // ---- one-time: weights (swizzled), b2/gamma ----
    for (int i = t; i < 2048; i += 256) {           // W1T: 256x8 units
        int r = i >> 3, c = i & 7;
        unsigned off = (unsigned)(r * 128 + ((c ^ (r & 7)) << 4));
        *reinterpret_cast<float4*>(smc + W1H_OFF + off) = reinterpret_cast<const float4*>(g_W1T_hi)[i];
        *reinterpret_cast<float4*>(smc + W1L_OFF + off) = reinterpret_cast<const float4*>(g_W1T_lo)[i];
    }
    for (int i = t; i < 2048; i += 256) {           // W2T: 64x32 units
        int r = i >> 5, c = i & 31;
        unsigned off = (unsigned)(r * 512 + ((c ^ (r & 7)) << 4));
        *reinterpret_cast<float4*>(smc + W2H_OFF + off) = reinterpret_cast<const float4*>(g_W2T_hi)[i];
        *reinterpret_cast<float4*>(smc + W2L_OFF + off) = reinterpret_cast<const float4*>(g_W2T_lo)[i];
    }
    if (t < 16)      reinterpret_cast<float4*>(smc + B2_OFF)[t]      = reinterpret_cast<const float4*>(b2)[t];
    else if (t < 32) reinterpret_cast<float4*>(smc + GM_OFF)[t - 16] = reinterpret_cast<const float4*>(gamma)[t - 16];
    int idx64 = g_idx64;

    // ---- prefetch first EA tile (512 units per buf) ----
    int tile = blockIdx.x;
    {
#pragma unroll
        for (int i = 0; i < 2; i++) {
            int u = t + i * 256;
            int r = u >> 3, c = u & 7;
            unsigned off = (unsigned)(r * 128 + ((c ^ (r & 7)) << 4));
            const char* srcH = (const char*)g_ea_hi + ((long long)tile * 64 + r) * 128 + c * 16;
            const char* srcL = (const char*)g_ea_lo + ((long long)tile * 64 + r) * 128 + c * 16;
            cp16(sb + EAH_OFF + off, srcH);
            cp16(sb + EAL_OFF + off, srcL);
        }
    }
    cp_commit();

    int m = wid & 3, hh = wid >> 2;      // GEMM1/GEMM2 role
    int grp = li >> 2, quad = li & 3;

    for (; tile < NT; tile += gridDim.x) {
        cp_wait_all();
        __syncthreads();                 // EA ready, H1 free

        // ---- A-frags (EA) into regs ----
        unsigned ah[4][4], al[4][4];
        {
            int ar = m * 16 + (li & 15);
#pragma unroll
            for (int j = 0; j < 4; j++) {
                int c = 2 * j + (li >> 4);
                unsigned off = (unsigned)(ar * 128 + ((c ^ (ar & 7)) << 4));
                ldx4(ah[j], sb + EAH_OFF + off);
                ldx4(al[j], sb + EAL_OFF + off);
            }
        }
        __syncthreads();                 // EA buffer free for prefetch

        // ---- prefetch next EA ----
        {
            int nt_ = tile + gridDim.x;
            if (nt_ < NT) {
#pragma unroll
                for (int i = 0; i < 2; i++) {
                    int u = t + i * 256;
                    int r = u >> 3, c = u & 7;
                    unsigned off = (unsigned)(r * 128 + ((c ^ (r & 7)) << 4));
                    const char* srcH = (const char*)g_ea_hi + ((long long)nt_ * 64 + r) * 128 + c * 16;
                    const char* srcL = (const char*)g_ea_lo + ((long long)nt_ * 64 + r) * 128 + c * 16;
                    cp16(sb + EAH_OFF + off, srcH);
                    cp16(sb + EAL_OFF + off, srcL);
                }
            }
            cp_commit();
        }

        // ---- edge indices for this thread's two rows ----
        long long e0 = (long long)tile * 64 + m * 16 + grp;   // row grp
        long long e1 = e0 + 8;                                // row grp+8
        int s0, t0, s1, t1;
        if (idx64) {
            s0 = (int)reinterpret_cast<const long long*>(eidx)[e0];
            t0 = (int)reinterpret_cast<const long long*>(eidx)[E_EDGES + e0];
            s1 = (int)reinterpret_cast<const long long*>(eidx)[e1];
            t1 = (int)reinterpret_cast<const long long*>(eidx)[E_EDGES + e1];
        } else {
            s0 = reinterpret_cast<const int*>(eidx)[e0];
            t0 = reinterpret_cast<const int*>(eidx)[E_EDGES + e0];
            s1 = reinterpret_cast<const int*>(eidx)[e1];
            t1 = reinterpret_cast<const int*>(eidx)[E_EDGES + e1];
        }
        const float* Ps0 = g_Ps + (long long)s0 * MSG;
        const float* Pt0 = g_Pt + (long long)t0 * MSG;
        const float* Ps1 = g_Ps + (long long)s1 * MSG;
        const float* Pt1 = g_Pt + (long long)t1 * MSG;

        // ---- GEMM1 + fused epilogue1, 16 n-tiles of 8 cols ----
        int r0s = m * 16 + grp;          // H1 row for c0/c1
        int r1s = r0s + 8;
#pragma unroll 4
        for (int nt2 = 0; nt2 < 16; nt2++) {
            int n0 = hh * 128 + nt2 * 8;
            int col0 = n0 + 2 * quad;
            // gather (independent of MMA; issued early)
            float2 ps0 = *reinterpret_cast<const float2*>(Ps0 + col0);
            float2 pt0 = *reinterpret_cast<const float2*>(Pt0 + col0);
            float2 ps1 = *reinterpret_cast<const float2*>(Ps1 + col0);
            float2 pt1 = *reinterpret_cast<const float2*>(Pt1 + col0);
            // B frags
            unsigned bh[4][2], bl[4][2];
            int bn = n0 + (li & 7);
#pragma unroll
            for (int j = 0; j < 4; j++) {
                int c = 2 * j + ((li >> 3) & 1);
                unsigned off = (unsigned)(bn * 128 + ((c ^ (bn & 7)) << 4));
                ldx2(bh[j], sb + W1H_OFF + off);
                ldx2(bl[j], sb + W1L_OFF + off);
            }
            float acc[4] = {0.f, 0.f, 0.f, 0.f};
#pragma unroll
            for (int j = 0; j < 4; j++) mma16816(acc, ah[j], bh[j]);
#pragma unroll
            for (int j = 0; j < 4; j++) mma16816(acc, ah[j], bl[j]);
#pragma unroll
            for (int j = 0; j < 4; j++) mma16816(acc, al[j], bh[j]);

            float v0 = lrelu(acc[0] + ps0.x + pt0.x);
            float v1 = lrelu(acc[1] + ps0.y + pt0.y);
            float v2 = lrelu(acc[2] + ps1.x + pt1.x);
            float v3 = lrelu(acc[3] + ps1.y + pt1.y);

            unsigned hpA = bfpack(v1, v0);
            unsigned hpB = bfpack(v3, v2);
            float hv0 = __uint_as_float(hpA << 16), hv1 = __uint_as_float(hpA & 0xffff0000u);
            float hv2 = __uint_as_float(hpB << 16), hv3 = __uint_as_float(hpB & 0xffff0000u);
            unsigned lpA = bfpack(v1 - hv1, v0 - hv0);
            unsigned lpB = bfpack(v3 - hv3, v2 - hv2);

            int cu = (n0 + 2 * quad) >> 3;             // 16B unit = column/8
            int ci = (2 * quad) & 7;                   // halfword pairs within unit
            unsigned offA = (unsigned)(r0s * 512 + ((cu ^ (r0s & 7)) << 4) + ci * 2);
            unsigned offB = (unsigned)(r1s * 512 + ((cu ^ (r1s & 7)) << 4) + ci * 2);
            *reinterpret_cast<unsigned*>(smc + H1H_OFF + offA) = hpA;
            *reinterpret_cast<unsigned*>(smc + H1L_OFF + offA) = lpA;
            *reinterpret_cast<unsigned*>(smc + H1H_OFF + offB) = hpB;
            *reinterpret_cast<unsigned*>(smc + H1L_OFF + offB) = lpB;
        }
        __syncthreads();                 // H1 complete

        // ---- GEMM2 (ALL 8 warps): warp = M-strip (m) x N-half (hh) ----
        float acc2[4][4];
#pragma unroll
        for (int n = 0; n < 4; n++)
#pragma unroll
            for (int q = 0; q < 4; q++) acc2[n][q] = 0.f;

        {
            int ar = m * 16 + (li & 15);
            for (int kf = 0; kf < 16; kf++) {
                unsigned a2h[4], a2l[4];
                int ca = 2 * kf + (li >> 4);
                unsigned offa = (unsigned)(ar * 512 + ((ca ^ (ar & 7)) << 4));
                ldx4(a2h, sb + H1H_OFF + offa);
                ldx4(a2l, sb + H1L_OFF + offa);
#pragma unroll
                for (int n = 0; n < 4; n++) {
                    unsigned b2h[2], b2l[2];
                    int bn = (hh * 4 + n) * 8 + (li & 7);
                    int cb = 2 * kf + ((li >> 3) & 1);
                    unsigned offb = (unsigned)(bn * 512 + ((cb ^ (bn & 7)) << 4));
                    ldx2(b2h, sb + W2H_OFF + offb);
                    ldx2(b2l, sb + W2L_OFF + offb);
                    mma16816(acc2[n], a2h, b2h);
                    mma16816(acc2[n], a2h, b2l);
                    mma16816(acc2[n], a2l, b2h);
                }
            }
        }

        // ---- epilogue2: +b2, partial ssq, cross-warp combine, store ------
        const float* b2s = reinterpret_cast<const float*>(smc + B2_OFF);
        const float* gms = reinterpret_cast<const float*>(smc + GM_OFF);
        float* sPart = reinterpret_cast<float*>(smc + SP_OFF);
        float v0[8], v1[8];
        float pr0 = 0.f, pr1 = 0.f;
#pragma unroll
        for (int n = 0; n < 4; n++) {
            int col = hh * 32 + n * 8 + 2 * quad;
            float ba = b2s[col], bb = b2s[col + 1];
            float a0 = acc2[n][0] + ba, a1 = acc2[n][1] + bb;
            float a2 = acc2[n][2] + ba, a3 = acc2[n][3] + bb;
            v0[n * 2] = a0; v0[n * 2 + 1] = a1;
            v1[n * 2] = a2; v1[n * 2 + 1] = a3;
            pr0 += a0 * a0 + a1 * a1;
            pr1 += a2 * a2 + a3 * a3;
        }
        pr0 += __shfl_xor_sync(0xffffffffu, pr0, 1);
        pr0 += __shfl_xor_sync(0xffffffffu, pr0, 2);
        pr1 += __shfl_xor_sync(0xffffffffu, pr1, 1);
        pr1 += __shfl_xor_sync(0xffffffffu, pr1, 2);
        int row0g = m * 16 + grp;
        if (quad == 0) {
            sPart[row0g * 2 + hh]       = pr0;
            sPart[(row0g + 8) * 2 + hh] = pr1;
        }
        __syncthreads();                 // partials visible + H1 reads done

        float ssq0 = sPart[row0g * 2] + sPart[row0g * 2 + 1];
        float ssq1 = sPart[(row0g + 8) * 2] + sPart[(row0g + 8) * 2 + 1];
        float sc0 = rsqrtf(ssq0 * (1.0f / 64.0f) + 1.1920929e-07f);
        float sc1 = rsqrtf(ssq1 * (1.0f / 64.0f) + 1.1920929e-07f);
        float* o0 = out + e0 * DIM;
        float* o1 = out + e1 * DIM;
#pragma unroll
        for (int n = 0; n < 4; n++) {
            int col = hh * 32 + n * 8 + 2 * quad;
            float ga = gms[col], gb = gms[col + 1];
            *reinterpret_cast<float2*>(o0 + col) =
                make_float2(v0[n * 2] * sc0 * ga, v0[n * 2 + 1] * sc0 * gb);
            *reinterpret_cast<float2*>(o1 + col) =
                make_float2(v1[n * 2] * sc1 * ga, v1[n * 2 + 1] * sc1 * gb);
        }
    }
}

// ---------------- launch ----------------------------------------------------
extern "C" void kernel_launch(void* const* d_in, const int* in_sizes, int n_in,
                              void* d_out, int out_size) {
    (void)in_sizes; (void)n_in; (void)out_size;
    const float* x_s   = (const float*)d_in[0];
    const float* x_t   = (const float*)d_in[1];
    const void*  eidx  = d_in[2];
    const float* ea    = (const float*)d_in[3];
    const float* xu    = (const float*)d_in[4];
    const float* W1    = (const float*)d_in[5];
    const float* b1    = (const float*)d_in[6];
    const float* W2    = (const float*)d_in[7];
    const float* b2    = (const float*)d_in[8];
    const float* gamma = (const float*)d_in[9];
    float* out = (float*)d_out;

    const int SMEM_PRE = (16384 + 64 * 68) * 4;   // 82944 B

    cudaFuncSetAttribute(node_pre_kernel, cudaFuncAttributeMaxDynamicSharedMemorySize, SMEM_PRE);
    cudaFuncSetAttribute(edge_mma_kernel, cudaFuncAttributeMaxDynamicSharedMemorySize, SMEM_EDGE);

    int nsm = 148;
    cudaDeviceGetAttribute(&nsm, cudaDevAttrMultiProcessorCount, 0);

    detect_idx_kernel<<<1, 32>>>((const unsigned*)eidx);
    cvec_kernel<<<1, MSG>>>(W1, b1, xu);
    split_ea_kernel<<<(E_EDGES * DIM / 4) / 256, 256>>>(ea);
    split_w_kernel<<<64, 256>>>(W1, W2);

    int pgrid = (N_NODES + 63) / 64;
    node_pre_kernel<<<pgrid, 256, SMEM_PRE>>>(x_s, W1,            0, N_NODES);
    node_pre_kernel<<<pgrid, 256, SMEM_PRE>>>(x_t, W1 + 64 * 256, 1, N_NODES);

    edge_mma_kernel<<<nsm, 256, SMEM_EDGE>>>(eidx, b2, gamma, out);
}

// round 15
// speedup vs baseline: 1.2409x; 1.2409x over previous
#include <cuda_runtime.h>
#include <cuda_bf16.h>

#define E_EDGES 1000000
#define N_NODES 50000
#define DIM     64
#define MSG     256
#define TILE_M  64
#define NT      (E_EDGES / TILE_M)      // 15625, exact

// ---------------- device-global scratch (no allocations) -------------------
__device__ __align__(16) float g_Ps[N_NODES * MSG];   // x_s@W1[0:64] + c
__device__ __align__(16) float g_Pt[N_NODES * MSG];   // x_t@W1[64:128]
__device__ __align__(16) float g_c[MSG];
__device__ int g_idx64;

__device__ __align__(16) __nv_bfloat16 g_ea_hi[E_EDGES * DIM];
__device__ __align__(16) __nv_bfloat16 g_ea_lo[E_EDGES * DIM];
__device__ __align__(16) __nv_bfloat16 g_W1T_hi[MSG * DIM];   // [256 n][64 k]
__device__ __align__(16) __nv_bfloat16 g_W1T_lo[MSG * DIM];
__device__ __align__(16) __nv_bfloat16 g_W2T_hi[DIM * MSG];   // [64 n][256 k]
__device__ __align__(16) __nv_bfloat16 g_W2T_lo[DIM * MSG];

// ---------------- helpers ---------------------------------------------------
__device__ __forceinline__ float2 ffma2(float2 a, float2 b, float2 c) {
    float2 d;
    asm("fma.rn.f32x2 %0, %1, %2, %3;"
        : "=l"(reinterpret_cast<unsigned long long &>(d))
        : "l"(reinterpret_cast<unsigned long long &>(a)),
          "l"(reinterpret_cast<unsigned long long &>(b)),
          "l"(reinterpret_cast<unsigned long long &>(c)));
    return d;
}
__device__ __forceinline__ float lrelu(float v) { return v >= 0.0f ? v : 0.01f * v; }

// pack: hi halfword = bf16(hv), lo halfword = bf16(lv)
__device__ __forceinline__ unsigned bfpack(float hv, float lv) {
    unsigned r;
    asm("cvt.rn.bf16x2.f32 %0, %1, %2;" : "=r"(r) : "f"(hv), "f"(lv));
    return r;
}
__device__ __forceinline__ void cp16(unsigned sa, const void* g) {
    asm volatile("cp.async.ca.shared.global [%0], [%1], 16;" :: "r"(sa), "l"(g));
}
__device__ __forceinline__ void cp_commit()  { asm volatile("cp.async.commit_group;"); }
__device__ __forceinline__ void cp_wait_all(){ asm volatile("cp.async.wait_group 0;"); }

__device__ __forceinline__ void ldx4(unsigned* r, unsigned a) {
    asm volatile("ldmatrix.sync.aligned.m8n8.x4.shared.b16 {%0,%1,%2,%3}, [%4];"
                 : "=r"(r[0]), "=r"(r[1]), "=r"(r[2]), "=r"(r[3]) : "r"(a));
}
__device__ __forceinline__ void ldx2(unsigned* r, unsigned a) {
    asm volatile("ldmatrix.sync.aligned.m8n8.x2.shared.b16 {%0,%1}, [%2];"
                 : "=r"(r[0]), "=r"(r[1]) : "r"(a));
}
__device__ __forceinline__ void mma16816(float* c, const unsigned* a, const unsigned* b) {
    asm volatile("mma.sync.aligned.m16n8k16.row.col.f32.bf16.bf16.f32 "
                 "{%0,%1,%2,%3}, {%4,%5,%6,%7}, {%8,%9}, {%0,%1,%2,%3};"
                 : "+f"(c[0]), "+f"(c[1]), "+f"(c[2]), "+f"(c[3])
                 : "r"(a[0]), "r"(a[1]), "r"(a[2]), "r"(a[3]), "r"(b[0]), "r"(b[1]));
}

// ---------------- prologue kernels ------------------------------------------
__global__ void detect_idx_kernel(const unsigned* __restrict__ idx) {
    if (threadIdx.x == 0) {
        int is64 = 1;
        for (int i = 0; i < 64; i++)
            if (idx[2 * i + 1] != 0u) { is64 = 0; break; }
        g_idx64 = is64;
    }
}

__global__ void cvec_kernel(const float* __restrict__ W1, const float* __restrict__ b1,
                            const float* __restrict__ xu) {
    int j = threadIdx.x;
    float acc = b1[j];
#pragma unroll 8
    for (int k = 0; k < DIM; k++) acc = fmaf(xu[k], W1[(192 + k) * MSG + j], acc);
    g_c[j] = acc;
}

__global__ __launch_bounds__(256) void split_ea_kernel(const float* __restrict__ ea) {
    long long i = (long long)blockIdx.x * 256 + threadIdx.x;   // float4 id
    float4 x = reinterpret_cast<const float4*>(ea)[i];
    unsigned hp0 = bfpack(x.y, x.x), hp1 = bfpack(x.w, x.z);
    float h0 = __uint_as_float(hp0 << 16), h1 = __uint_as_float(hp0 & 0xffff0000u);
    float h2 = __uint_as_float(hp1 << 16), h3 = __uint_as_float(hp1 & 0xffff0000u);
    unsigned lp0 = bfpack(x.y - h1, x.x - h0), lp1 = bfpack(x.w - h3, x.z - h2);
    reinterpret_cast<uint2*>(g_ea_hi)[i] = make_uint2(hp0, hp1);
    reinterpret_cast<uint2*>(g_ea_lo)[i] = make_uint2(lp0, lp1);
}

__global__ void split_w_kernel(const float* __restrict__ W1, const float* __restrict__ W2) {
    int i = blockIdx.x * 256 + threadIdx.x;   // 0..16383
    {   // W1T[n][k] = W1[(128+k)*256+n]
        int n = i >> 6, k = i & 63;
        float x = W1[(128 + k) * MSG + n];
        __nv_bfloat16 h = __float2bfloat16(x);
        g_W1T_hi[i] = h;
        g_W1T_lo[i] = __float2bfloat16(x - __bfloat162float(h));
    }
    {   // W2T[n][k] = W2[k*64+n]
        int n = i >> 8, k = i & 255;
        float x = W2[k * DIM + n];
        __nv_bfloat16 h = __float2bfloat16(x);
        g_W2T_hi[i] = h;
        g_W2T_lo[i] = __float2bfloat16(x - __bfloat162float(h));
    }
}

// ---------------- node precompute (fp32; c folded into Ps) ------------------
__global__ __launch_bounds__(256, 1)
void node_pre_kernel(const float* __restrict__ X, const float* __restrict__ Wsub,
                     int which, int N) {
    extern __shared__ float sm[];
    float* sW = sm;
    float* sA = sm + 16384;
    float* P  = which ? g_Pt : g_Ps;

    int t = threadIdx.x;
    int row0 = blockIdx.x * 64;
#pragma unroll
    for (int i = 0; i < 16; i++) {
        int idx = t + i * 256;
        reinterpret_cast<float4*>(sW)[idx] = reinterpret_cast<const float4*>(Wsub)[idx];
    }
#pragma unroll
    for (int i = 0; i < 4; i++) {
        int f = t + i * 256;
        int r = f >> 4, q = f & 15;
        float4 v = make_float4(0.f, 0.f, 0.f, 0.f);
        if (row0 + r < N) v = reinterpret_cast<const float4*>(X)[(row0 + r) * 16 + q];
        *reinterpret_cast<float4*>(&sA[r * 68 + q * 4]) = v;
    }
    __syncthreads();

    int tx = t & 31, ty = t >> 5;
    float2 acc[8][4];
#pragma unroll
    for (int e = 0; e < 8; e++)
#pragma unroll
        for (int j = 0; j < 4; j++) acc[e][j] = make_float2(0.f, 0.f);

    for (int k4 = 0; k4 < 64; k4 += 4) {
        float4 a[8];
#pragma unroll
        for (int e = 0; e < 8; e++)
            a[e] = *reinterpret_cast<const float4*>(&sA[(ty * 8 + e) * 68 + k4]);
#pragma unroll
        for (int kk = 0; kk < 4; kk++) {
            float4 b0 = *reinterpret_cast<const float4*>(&sW[(k4 + kk) * 256 + tx * 4]);
            float4 b1 = *reinterpret_cast<const float4*>(&sW[(k4 + kk) * 256 + 128 + tx * 4]);
#pragma unroll
            for (int e = 0; e < 8; e++) {
                float av = (kk == 0) ? a[e].x : (kk == 1) ? a[e].y : (kk == 2) ? a[e].z : a[e].w;
                float2 ad = make_float2(av, av);
                acc[e][0] = ffma2(ad, make_float2(b0.x, b0.y), acc[e][0]);
                acc[e][1] = ffma2(ad, make_float2(b0.z, b0.w), acc[e][1]);
                acc[e][2] = ffma2(ad, make_float2(b1.x, b1.y), acc[e][2]);
                acc[e][3] = ffma2(ad, make_float2(b1.z, b1.w), acc[e][3]);
            }
        }
    }

    float4 c0 = make_float4(0.f, 0.f, 0.f, 0.f), c1 = c0;
    if (which == 0) {
        c0 = *reinterpret_cast<const float4*>(&g_c[tx * 4]);
        c1 = *reinterpret_cast<const float4*>(&g_c[128 + tx * 4]);
    }
#pragma unroll
    for (int e = 0; e < 8; e++) {
        int r = row0 + ty * 8 + e;
        if (r < N) {
            float4 o0 = make_float4(acc[e][0].x + c0.x, acc[e][0].y + c0.y,
                                    acc[e][1].x + c0.z, acc[e][1].y + c0.w);
            float4 o1 = make_float4(acc[e][2].x + c1.x, acc[e][2].y + c1.y,
                                    acc[e][3].x + c1.z, acc[e][3].y + c1.w);
            *reinterpret_cast<float4*>(&P[r * 256 + tx * 4])       = o0;
            *reinterpret_cast<float4*>(&P[r * 256 + 128 + tx * 4]) = o1;
        }
    }
}

// ---------------- HMMA edge kernel ------------------------------------------
// smem map (bytes). 16B-unit XOR swizzle: unit c -> c ^ (row & 7)
#define W1H_OFF 0          // 256 rows x 128B
#define W1L_OFF 32768
#define W2H_OFF 65536      // 64 rows x 512B
#define W2L_OFF 98304
#define H1H_OFF 131072     // 64 rows x 512B
#define H1L_OFF 163840
#define EAH_OFF 196608     // 64 rows x 128B
#define EAL_OFF 204800
#define B2_OFF  212992     // 64 f32
#define GM_OFF  213248     // 64 f32
#define SMEM_EDGE 213504

__global__ __launch_bounds__(256, 1)
void edge_mma_kernel(const void* __restrict__ eidx, const float* __restrict__ b2,
                     const float* __restrict__ gamma, float* __restrict__ out) {
    extern __shared__ char smc[];
    unsigned sb = (unsigned)__cvta_generic_to_shared(smc);
    int t = threadIdx.x, wid = t >> 5, li = t & 31;

    // ---- one-time: weights (swizzled), b2/gamma ----
    for (int i = t; i < 2048; i += 256) {           // W1T: 256x8 units
        int r = i >> 3, c = i & 7;
        unsigned off = (unsigned)(r * 128 + ((c ^ (r & 7)) << 4));
        *reinterpret_cast<float4*>(smc + W1H_OFF + off) = reinterpret_cast<const float4*>(g_W1T_hi)[i];
        *reinterpret_cast<float4*>(smc + W1L_OFF + off) = reinterpret_cast<const float4*>(g_W1T_lo)[i];
    }
    for (int i = t; i < 2048; i += 256) {           // W2T: 64x32 units
        int r = i >> 5, c = i & 31;
        unsigned off = (unsigned)(r * 512 + ((c ^ (r & 7)) << 4));
        *reinterpret_cast<float4*>(smc + W2H_OFF + off) = reinterpret_cast<const float4*>(g_W2T_hi)[i];
        *reinterpret_cast<float4*>(smc + W2L_OFF + off) = reinterpret_cast<const float4*>(g_W2T_lo)[i];
    }
    if (t < 16)      reinterpret_cast<float4*>(smc + B2_OFF)[t]      = reinterpret_cast<const float4*>(b2)[t];
    else if (t < 32) reinterpret_cast<float4*>(smc + GM_OFF)[t - 16] = reinterpret_cast<const float4*>(gamma)[t - 16];
    int idx64 = g_idx64;

    // ---- prefetch first EA tile (512 units per buf) ----
    int tile = blockIdx.x;
    {
#pragma unroll
        for (int i = 0; i < 2; i++) {
            int u = t + i * 256;
            int r = u >> 3, c = u & 7;
            unsigned off = (unsigned)(r * 128 + ((c ^ (r & 7)) << 4));
            const char* srcH = (const char*)g_ea_hi + ((long long)tile * 64 + r) * 128 + c * 16;
            const char* srcL = (const char*)g_ea_lo + ((long long)tile * 64 + r) * 128 + c * 16;
            cp16(sb + EAH_OFF + off, srcH);
            cp16(sb + EAL_OFF + off, srcL);
        }
    }
    cp_commit();

    int m = wid & 3, hh = wid >> 2;      // GEMM1 role
    int grp = li >> 2, quad = li & 3;

    for (; tile < NT; tile += gridDim.x) {
        cp_wait_all();
        __syncthreads();                 // EA ready, H1 free

        // ---- A-frags (EA) into regs ----
        unsigned ah[4][4], al[4][4];
        {
            int ar = m * 16 + (li & 15);
#pragma unroll
            for (int j = 0; j < 4; j++) {
                int c = 2 * j + (li >> 4);
                unsigned off = (unsigned)(ar * 128 + ((c ^ (ar & 7)) << 4));
                ldx4(ah[j], sb + EAH_OFF + off);
                ldx4(al[j], sb + EAL_OFF + off);
            }
        }
        __syncthreads();                 // EA buffer free for prefetch

        // ---- prefetch next EA ----
        {
            int nt_ = tile + gridDim.x;
            if (nt_ < NT) {
#pragma unroll
                for (int i = 0; i < 2; i++) {
                    int u = t + i * 256;
                    int r = u >> 3, c = u & 7;
                    unsigned off = (unsigned)(r * 128 + ((c ^ (r & 7)) << 4));
                    const char* srcH = (const char*)g_ea_hi + ((long long)nt_ * 64 + r) * 128 + c * 16;
                    const char* srcL = (const char*)g_ea_lo + ((long long)nt_ * 64 + r) * 128 + c * 16;
                    cp16(sb + EAH_OFF + off, srcH);
                    cp16(sb + EAL_OFF + off, srcL);
                }
            }
            cp_commit();
        }

        // ---- edge indices for this thread's two rows ----
        long long e0 = (long long)tile * 64 + m * 16 + grp;   // row grp
        long long e1 = e0 + 8;                                // row grp+8
        int s0, t0, s1, t1;
        if (idx64) {
            s0 = (int)reinterpret_cast<const long long*>(eidx)[e0];
            t0 = (int)reinterpret_cast<const long long*>(eidx)[E_EDGES + e0];
            s1 = (int)reinterpret_cast<const long long*>(eidx)[e1];
            t1 = (int)reinterpret_cast<const long long*>(eidx)[E_EDGES + e1];
        } else {
            s0 = reinterpret_cast<const int*>(eidx)[e0];
            t0 = reinterpret_cast<const int*>(eidx)[E_EDGES + e0];
            s1 = reinterpret_cast<const int*>(eidx)[e1];
            t1 = reinterpret_cast<const int*>(eidx)[E_EDGES + e1];
        }
        const float* Ps0 = g_Ps + (long long)s0 * MSG;
        const float* Pt0 = g_Pt + (long long)t0 * MSG;
        const float* Ps1 = g_Ps + (long long)s1 * MSG;
        const float* Pt1 = g_Pt + (long long)t1 * MSG;

        // ---- GEMM1 + fused epilogue1, 16 n-tiles of 8 cols ----
        // gather software-pipelined one iteration ahead
        int r0s = m * 16 + grp;          // H1 row
        int r1s = r0s + 8;
        int colp = hh * 128 + 2 * quad;  // nt2=0 column
        float2 ps0 = *reinterpret_cast<const float2*>(Ps0 + colp);
        float2 pt0 = *reinterpret_cast<const float2*>(Pt0 + colp);
        float2 ps1 = *reinterpret_cast<const float2*>(Ps1 + colp);
        float2 pt1 = *reinterpret_cast<const float2*>(Pt1 + colp);
#pragma unroll 4
        for (int nt2 = 0; nt2 < 16; nt2++) {
            int n0 = hh * 128 + nt2 * 8;
            // consume current gather; prefetch next iteration's
            float2 cps0 = ps0, cpt0 = pt0, cps1 = ps1, cpt1 = pt1;
            if (nt2 < 15) {
                int coln = n0 + 8 + 2 * quad;
                ps0 = *reinterpret_cast<const float2*>(Ps0 + coln);
                pt0 = *reinterpret_cast<const float2*>(Pt0 + coln);
                ps1 = *reinterpret_cast<const float2*>(Ps1 + coln);
                pt1 = *reinterpret_cast<const float2*>(Pt1 + coln);
            }
            // B frags
            unsigned bh[4][2], bl[4][2];
            int bn = n0 + (li & 7);
#pragma unroll
            for (int j = 0; j < 4; j++) {
                int c = 2 * j + ((li >> 3) & 1);
                unsigned off = (unsigned)(bn * 128 + ((c ^ (bn & 7)) << 4));
                ldx2(bh[j], sb + W1H_OFF + off);
                ldx2(bl[j], sb + W1L_OFF + off);
            }
            float acc[4] = {0.f, 0.f, 0.f, 0.f};
#pragma unroll
            for (int j = 0; j < 4; j++) mma16816(acc, ah[j], bh[j]);
#pragma unroll
            for (int j = 0; j < 4; j++) mma16816(acc, ah[j], bl[j]);
#pragma unroll
            for (int j = 0; j < 4; j++) mma16816(acc, al[j], bh[j]);

            float v0 = lrelu(acc[0] + cps0.x + cpt0.x);
            float v1 = lrelu(acc[1] + cps0.y + cpt0.y);
            float v2 = lrelu(acc[2] + cps1.x + cpt1.x);
            float v3 = lrelu(acc[3] + cps1.y + cpt1.y);

            unsigned hpA = bfpack(v1, v0);
            unsigned hpB = bfpack(v3, v2);
            float hv0 = __uint_as_float(hpA << 16), hv1 = __uint_as_float(hpA & 0xffff0000u);
            float hv2 = __uint_as_float(hpB << 16), hv3 = __uint_as_float(hpB & 0xffff0000u);
            unsigned lpA = bfpack(v1 - hv1, v0 - hv0);
            unsigned lpB = bfpack(v3 - hv3, v2 - hv2);

            int cu = (n0 + 2 * quad) >> 3;             // 16B unit = column/8
            int ci = (2 * quad) & 7;
            unsigned offA = (unsigned)(r0s * 512 + ((cu ^ (r0s & 7)) << 4) + ci * 2);
            unsigned offB = (unsigned)(r1s * 512 + ((cu ^ (r1s & 7)) << 4) + ci * 2);
            *reinterpret_cast<unsigned*>(smc + H1H_OFF + offA) = hpA;
            *reinterpret_cast<unsigned*>(smc + H1L_OFF + offA) = lpA;
            *reinterpret_cast<unsigned*>(smc + H1H_OFF + offB) = hpB;
            *reinterpret_cast<unsigned*>(smc + H1L_OFF + offB) = lpB;
        }
        __syncthreads();                 // H1 complete

        // ---- GEMM2 (warps 0-3): D2[64,64] = H1 @ W2T^T ----
        if (wid < 4) {
            float acc2[8][4];
#pragma unroll
            for (int n = 0; n < 8; n++)
#pragma unroll
                for (int q = 0; q < 4; q++) acc2[n][q] = 0.f;

            int ar = wid * 16 + (li & 15);
            for (int kf = 0; kf < 16; kf++) {
                unsigned a2h[4], a2l[4];
                int ca = 2 * kf + (li >> 4);
                unsigned offa = (unsigned)(ar * 512 + ((ca ^ (ar & 7)) << 4));
                ldx4(a2h, sb + H1H_OFF + offa);
                ldx4(a2l, sb + H1L_OFF + offa);
#pragma unroll
                for (int n = 0; n < 8; n++) {
                    unsigned b2h[2], b2l[2];
                    int bn = n * 8 + (li & 7);
                    int cb = 2 * kf + ((li >> 3) & 1);
                    unsigned offb = (unsigned)(bn * 512 + ((cb ^ (bn & 7)) << 4));
                    ldx2(b2h, sb + W2H_OFF + offb);
                    ldx2(b2l, sb + W2L_OFF + offb);
                    mma16816(acc2[n], a2h, b2h);
                    mma16816(acc2[n], a2h, b2l);
                    mma16816(acc2[n], a2l, b2h);
                }
            }

            // ---- epilogue2: +b2, RMSNorm, *gamma, store ----
            const float* b2s = reinterpret_cast<const float*>(smc + B2_OFF);
            const float* gms = reinterpret_cast<const float*>(smc + GM_OFF);
            long long ee0 = (long long)tile * 64 + wid * 16 + grp;
            long long ee1 = ee0 + 8;
            float v0[16], v1[16], ssq0 = 0.f, ssq1 = 0.f;
#pragma unroll
            for (int n = 0; n < 8; n++) {
                int col = n * 8 + 2 * quad;
                float ba = b2s[col], bb = b2s[col + 1];
                float a0 = acc2[n][0] + ba, a1 = acc2[n][1] + bb;
                float a2 = acc2[n][2] + ba, a3 = acc2[n][3] + bb;
                v0[n * 2] = a0; v0[n * 2 + 1] = a1;
                v1[n * 2] = a2; v1[n * 2 + 1] = a3;
                ssq0 += a0 * a0 + a1 * a1;
                ssq1 += a2 * a2 + a3 * a3;
            }
            ssq0 += __shfl_xor_sync(0xffffffffu, ssq0, 1);
            ssq0 += __shfl_xor_sync(0xffffffffu, ssq0, 2);
            ssq1 += __shfl_xor_sync(0xffffffffu, ssq1, 1);
            ssq1 += __shfl_xor_sync(0xffffffffu, ssq1, 2);
            float sc0 = rsqrtf(ssq0 * (1.0f / 64.0f) + 1.1920929e-07f);
            float sc1 = rsqrtf(ssq1 * (1.0f / 64.0f) + 1.1920929e-07f);
            float* o0 = out + ee0 * DIM;
            float* o1 = out + ee1 * DIM;
#pragma unroll
            for (int n = 0; n < 8; n++) {
                int col = n * 8 + 2 * quad;
                float ga = gms[col], gb = gms[col + 1];
                *reinterpret_cast<float2*>(o0 + col) =
                    make_float2(v0[n * 2] * sc0 * ga, v0[n * 2 + 1] * sc0 * gb);
                *reinterpret_cast<float2*>(o1 + col) =
                    make_float2(v1[n * 2] * sc1 * ga, v1[n * 2 + 1] * sc1 * gb);
            }
        }
        __syncthreads();                 // H1 free for next tile
    }
}

// ---------------- launch ----------------------------------------------------
extern "C" void kernel_launch(void* const* d_in, const int* in_sizes, int n_in,
                              void* d_out, int out_size) {
    (void)in_sizes; (void)n_in; (void)out_size;
    const float* x_s   = (const float*)d_in[0];
    const float* x_t   = (const float*)d_in[1];
    const void*  eidx  = d_in[2];
    const float* ea    = (const float*)d_in[3];
    const float* xu    = (const float*)d_in[4];
    const float* W1    = (const float*)d_in[5];
    const float* b1    = (const float*)d_in[6];
    const float* W2    = (const float*)d_in[7];
    const float* b2    = (const float*)d_in[8];
    const float* gamma = (const float*)d_in[9];
    float* out = (float*)d_out;

    const int SMEM_PRE = (16384 + 64 * 68) * 4;   // 82944 B

    cudaFuncSetAttribute(node_pre_kernel, cudaFuncAttributeMaxDynamicSharedMemorySize, SMEM_PRE);
    cudaFuncSetAttribute(edge_mma_kernel, cudaFuncAttributeMaxDynamicSharedMemorySize, SMEM_EDGE);

    int nsm = 148;
    cudaDeviceGetAttribute(&nsm, cudaDevAttrMultiProcessorCount, 0);

    detect_idx_kernel<<<1, 32>>>((const unsigned*)eidx);
    cvec_kernel<<<1, MSG>>>(W1, b1, xu);
    split_ea_kernel<<<(E_EDGES * DIM / 4) / 256, 256>>>(ea);
    split_w_kernel<<<64, 256>>>(W1, W2);

    int pgrid = (N_NODES + 63) / 64;
    node_pre_kernel<<<pgrid, 256, SMEM_PRE>>>(x_s, W1,            0, N_NODES);
    node_pre_kernel<<<pgrid, 256, SMEM_PRE>>>(x_t, W1 + 64 * 256, 1, N_NODES);

    edge_mma_kernel<<<nsm, 256, SMEM_EDGE>>>(eidx, b2, gamma, out);
}

// round 16
// speedup vs baseline: 1.3205x; 1.0641x over previous
#include <cuda_runtime.h>
#include <cuda_bf16.h>

#define E_EDGES 1000000
#define N_NODES 50000
#define DIM     64
#define MSG     256
#define TILE_M  64
#define NT      (E_EDGES / TILE_M)      // 15625, exact

// ---------------- device-global scratch (no allocations) -------------------
__device__ __align__(16) float g_Ps[N_NODES * MSG];   // x_s@W1[0:64] + c
__device__ __align__(16) float g_Pt[N_NODES * MSG];   // x_t@W1[64:128]
__device__ __align__(16) float g_c[MSG];
__device__ int g_idx64;

__device__ __align__(16) __nv_bfloat16 g_ea_hi[E_EDGES * DIM];
__device__ __align__(16) __nv_bfloat16 g_ea_lo[E_EDGES * DIM];
__device__ __align__(16) __nv_bfloat16 g_W1T_hi[MSG * DIM];   // [256 n][64 k]
__device__ __align__(16) __nv_bfloat16 g_W1T_lo[MSG * DIM];
__device__ __align__(16) __nv_bfloat16 g_W2T_hi[DIM * MSG];   // [64 n][256 k]
__device__ __align__(16) __nv_bfloat16 g_W2T_lo[DIM * MSG];

// ---------------- helpers ---------------------------------------------------
__device__ __forceinline__ float2 ffma2(float2 a, float2 b, float2 c) {
    float2 d;
    asm("fma.rn.f32x2 %0, %1, %2, %3;"
        : "=l"(reinterpret_cast<unsigned long long &>(d))
        : "l"(reinterpret_cast<unsigned long long &>(a)),
          "l"(reinterpret_cast<unsigned long long &>(b)),
          "l"(reinterpret_cast<unsigned long long &>(c)));
    return d;
}
__device__ __forceinline__ float lrelu(float v) { return v >= 0.0f ? v : 0.01f * v; }

// pack: hi halfword = bf16(hv), lo halfword = bf16(lv)
__device__ __forceinline__ unsigned bfpack(float hv, float lv) {
    unsigned r;
    asm("cvt.rn.bf16x2.f32 %0, %1, %2;" : "=r"(r) : "f"(hv), "f"(lv));
    return r;
}
__device__ __forceinline__ void cp16(unsigned sa, const void* g) {
    asm volatile("cp.async.ca.shared.global [%0], [%1], 16;" :: "r"(sa), "l"(g));
}
__device__ __forceinline__ void cp_commit()  { asm volatile("cp.async.commit_group;"); }
__device__ __forceinline__ void cp_wait_all(){ asm volatile("cp.async.wait_group 0;"); }

__device__ __forceinline__ void ldx4(unsigned* r, unsigned a) {
    asm volatile("ldmatrix.sync.aligned.m8n8.x4.shared.b16 {%0,%1,%2,%3}, [%4];"
                 : "=r"(r[0]), "=r"(r[1]), "=r"(r[2]), "=r"(r[3]) : "r"(a));
}
__device__ __forceinline__ void mma16816(float* c, const unsigned* a, const unsigned* b) {
    asm volatile("mma.sync.aligned.m16n8k16.row.col.f32.bf16.bf16.f32 "
                 "{%0,%1,%2,%3}, {%4,%5,%6,%7}, {%8,%9}, {%0,%1,%2,%3};"
                 : "+f"(c[0]), "+f"(c[1]), "+f"(c[2]), "+f"(c[3])
                 : "r"(a[0]), "r"(a[1]), "r"(a[2]), "r"(a[3]), "r"(b[0]), "r"(b[1]));
}

// ---------------- prologue kernels ------------------------------------------
__global__ void detect_idx_kernel(const unsigned* __restrict__ idx) {
    if (threadIdx.x == 0) {
        int is64 = 1;
        for (int i = 0; i < 64; i++)
            if (idx[2 * i + 1] != 0u) { is64 = 0; break; }
        g_idx64 = is64;
    }
}

__global__ void cvec_kernel(const float* __restrict__ W1, const float* __restrict__ b1,
                            const float* __restrict__ xu) {
    int j = threadIdx.x;
    float acc = b1[j];
#pragma unroll 8
    for (int k = 0; k < DIM; k++) acc = fmaf(xu[k], W1[(192 + k) * MSG + j], acc);
    g_c[j] = acc;
}

__global__ __launch_bounds__(256) void split_ea_kernel(const float* __restrict__ ea) {
    long long i = (long long)blockIdx.x * 256 + threadIdx.x;   // float4 id
    float4 x = reinterpret_cast<const float4*>(ea)[i];
    unsigned hp0 = bfpack(x.y, x.x), hp1 = bfpack(x.w, x.z);
    float h0 = __uint_as_float(hp0 << 16), h1 = __uint_as_float(hp0 & 0xffff0000u);
    float h2 = __uint_as_float(hp1 << 16), h3 = __uint_as_float(hp1 & 0xffff0000u);
    unsigned lp0 = bfpack(x.y - h1, x.x - h0), lp1 = bfpack(x.w - h3, x.z - h2);
    reinterpret_cast<uint2*>(g_ea_hi)[i] = make_uint2(hp0, hp1);
    reinterpret_cast<uint2*>(g_ea_lo)[i] = make_uint2(lp0, lp1);
}

__global__ void split_w_kernel(const float* __restrict__ W1, const float* __restrict__ W2) {
    int i = blockIdx.x * 256 + threadIdx.x;   // 0..16383
    {   // W1T[n][k] = W1[(128+k)*256+n]
        int n = i >> 6, k = i & 63;
        float x = W1[(128 + k) * MSG + n];
        __nv_bfloat16 h = __float2bfloat16(x);
        g_W1T_hi[i] = h;
        g_W1T_lo[i] = __float2bfloat16(x - __bfloat162float(h));
    }
    {   // W2T[n][k] = W2[k*64+n]
        int n = i >> 8, k = i & 255;
        float x = W2[k * DIM + n];
        __nv_bfloat16 h = __float2bfloat16(x);
        g_W2T_hi[i] = h;
        g_W2T_lo[i] = __float2bfloat16(x - __bfloat162float(h));
    }
}

// ---------------- node precompute (fp32; c folded into Ps) ------------------
__global__ __launch_bounds__(256, 1)
void node_pre_kernel(const float* __restrict__ X, const float* __restrict__ Wsub,
                     int which, int N) {
    extern __shared__ float sm[];
    float* sW = sm;
    float* sA = sm + 16384;
    float* P  = which ? g_Pt : g_Ps;

    int t = threadIdx.x;
    int row0 = blockIdx.x * 64;
#pragma unroll
    for (int i = 0; i < 16; i++) {
        int idx = t + i * 256;
        reinterpret_cast<float4*>(sW)[idx] = reinterpret_cast<const float4*>(Wsub)[idx];
    }
#pragma unroll
    for (int i = 0; i < 4; i++) {
        int f = t + i * 256;
        int r = f >> 4, q = f & 15;
        float4 v = make_float4(0.f, 0.f, 0.f, 0.f);
        if (row0 + r < N) v = reinterpret_cast<const float4*>(X)[(row0 + r) * 16 + q];
        *reinterpret_cast<float4*>(&sA[r * 68 + q * 4]) = v;
    }
    __syncthreads();

    int tx = t & 31, ty = t >> 5;
    float2 acc[8][4];
#pragma unroll
    for (int e = 0; e < 8; e++)
#pragma unroll
        for (int j = 0; j < 4; j++) acc[e][j] = make_float2(0.f, 0.f);

    for (int k4 = 0; k4 < 64; k4 += 4) {
        float4 a[8];
#pragma unroll
        for (int e = 0; e < 8; e++)
            a[e] = *reinterpret_cast<const float4*>(&sA[(ty * 8 + e) * 68 + k4]);
#pragma unroll
        for (int kk = 0; kk < 4; kk++) {
            float4 b0 = *reinterpret_cast<const float4*>(&sW[(k4 + kk) * 256 + tx * 4]);
            float4 b1 = *reinterpret_cast<const float4*>(&sW[(k4 + kk) * 256 + 128 + tx * 4]);
#pragma unroll
            for (int e = 0; e < 8; e++) {
                float av = (kk == 0) ? a[e].x : (kk == 1) ? a[e].y : (kk == 2) ? a[e].z : a[e].w;
                float2 ad = make_float2(av, av);
                acc[e][0] = ffma2(ad, make_float2(b0.x, b0.y), acc[e][0]);
                acc[e][1] = ffma2(ad, make_float2(b0.z, b0.w), acc[e][1]);
                acc[e][2] = ffma2(ad, make_float2(b1.x, b1.y), acc[e][2]);
                acc[e][3] = ffma2(ad, make_float2(b1.z, b1.w), acc[e][3]);
            }
        }
    }

    float4 c0 = make_float4(0.f, 0.f, 0.f, 0.f), c1 = c0;
    if (which == 0) {
        c0 = *reinterpret_cast<const float4*>(&g_c[tx * 4]);
        c1 = *reinterpret_cast<const float4*>(&g_c[128 + tx * 4]);
    }
#pragma unroll
    for (int e = 0; e < 8; e++) {
        int r = row0 + ty * 8 + e;
        if (r < N) {
            float4 o0 = make_float4(acc[e][0].x + c0.x, acc[e][0].y + c0.y,
                                    acc[e][1].x + c0.z, acc[e][1].y + c0.w);
            float4 o1 = make_float4(acc[e][2].x + c1.x, acc[e][2].y + c1.y,
                                    acc[e][3].x + c1.z, acc[e][3].y + c1.w);
            *reinterpret_cast<float4*>(&P[r * 256 + tx * 4])       = o0;
            *reinterpret_cast<float4*>(&P[r * 256 + 128 + tx * 4]) = o1;
        }
    }
}

// ---------------- HMMA edge kernel ------------------------------------------
// smem map (bytes). 16B-unit XOR swizzle: unit c -> c ^ (row & 7)
#define W1H_OFF 0          // 256 rows x 128B
#define W1L_OFF 32768
#define W2H_OFF 65536      // 64 rows x 512B
#define W2L_OFF 98304
#define H1H_OFF 131072     // 64 rows x 512B
#define H1L_OFF 163840
#define EAH_OFF 196608     // 64 rows x 128B
#define EAL_OFF 204800
#define B2_OFF  212992     // 64 f32
#define GM_OFF  213248     // 64 f32
#define SMEM_EDGE 213504

__global__ __launch_bounds__(256, 1)
void edge_mma_kernel(const void* __restrict__ eidx, const float* __restrict__ b2,
                     const float* __restrict__ gamma, float* __restrict__ out) {
    extern __shared__ char smc[];
    unsigned sb = (unsigned)__cvta_generic_to_shared(smc);
    int t = threadIdx.x, wid = t >> 5, li = t & 31;

    // ---- one-time: weights (swizzled), b2/gamma ----
    for (int i = t; i < 2048; i += 256) {           // W1T: 256x8 units
        int r = i >> 3, c = i & 7;
        unsigned off = (unsigned)(r * 128 + ((c ^ (r & 7)) << 4));
        *reinterpret_cast<float4*>(smc + W1H_OFF + off) = reinterpret_cast<const float4*>(g_W1T_hi)[i];
        *reinterpret_cast<float4*>(smc + W1L_OFF + off) = reinterpret_cast<const float4*>(g_W1T_lo)[i];
    }
    for (int i = t; i < 2048; i += 256) {           // W2T: 64x32 units
        int r = i >> 5, c = i & 31;
        unsigned off = (unsigned)(r * 512 + ((c ^ (r & 7)) << 4));
        *reinterpret_cast<float4*>(smc + W2H_OFF + off) = reinterpret_cast<const float4*>(g_W2T_hi)[i];
        *reinterpret_cast<float4*>(smc + W2L_OFF + off) = reinterpret_cast<const float4*>(g_W2T_lo)[i];
    }
    if (t < 16)      reinterpret_cast<float4*>(smc + B2_OFF)[t]      = reinterpret_cast<const float4*>(b2)[t];
    else if (t < 32) reinterpret_cast<float4*>(smc + GM_OFF)[t - 16] = reinterpret_cast<const float4*>(gamma)[t - 16];
    int idx64 = g_idx64;

    // ---- prefetch first EA tile (512 units per buf) ----
    int tile = blockIdx.x;
    {
#pragma unroll
        for (int i = 0; i < 2; i++) {
            int u = t + i * 256;
            int r = u >> 3, c = u & 7;
            unsigned off = (unsigned)(r * 128 + ((c ^ (r & 7)) << 4));
            const char* srcH = (const char*)g_ea_hi + ((long long)tile * 64 + r) * 128 + c * 16;
            const char* srcL = (const char*)g_ea_lo + ((long long)tile * 64 + r) * 128 + c * 16;
            cp16(sb + EAH_OFF + off, srcH);
            cp16(sb + EAL_OFF + off, srcL);
        }
    }
    cp_commit();

    int m = wid & 3, hh = wid >> 2;      // GEMM1 role
    int grp = li >> 2, quad = li & 3;

    for (; tile < NT; tile += gridDim.x) {
        cp_wait_all();
        __syncthreads();                 // EA ready, H1 free

        // ---- A-frags (EA) into regs ----
        unsigned ah[4][4], al[4][4];
        {
            int ar = m * 16 + (li & 15);
#pragma unroll
            for (int j = 0; j < 4; j++) {
                int c = 2 * j + (li >> 4);
                unsigned off = (unsigned)(ar * 128 + ((c ^ (ar & 7)) << 4));
                ldx4(ah[j], sb + EAH_OFF + off);
                ldx4(al[j], sb + EAL_OFF + off);
            }
        }
        __syncthreads();                 // EA buffer free for prefetch

        // ---- prefetch next EA ----
        {
            int nt_ = tile + gridDim.x;
            if (nt_ < NT) {
#pragma unroll
                for (int i = 0; i < 2; i++) {
                    int u = t + i * 256;
                    int r = u >> 3, c = u & 7;
                    unsigned off = (unsigned)(r * 128 + ((c ^ (r & 7)) << 4));
                    const char* srcH = (const char*)g_ea_hi + ((long long)nt_ * 64 + r) * 128 + c * 16;
                    const char* srcL = (const char*)g_ea_lo + ((long long)nt_ * 64 + r) * 128 + c * 16;
                    cp16(sb + EAH_OFF + off, srcH);
                    cp16(sb + EAL_OFF + off, srcL);
                }
            }
            cp_commit();
        }

        // ---- edge indices for this thread's two rows ----
        long long e0 = (long long)tile * 64 + m * 16 + grp;   // row grp
        long long e1 = e0 + 8;                                // row grp+8
        int s0, t0, s1, t1;
        if (idx64) {
            s0 = (int)reinterpret_cast<const long long*>(eidx)[e0];
            t0 = (int)reinterpret_cast<const long long*>(eidx)[E_EDGES + e0];
            s1 = (int)reinterpret_cast<const long long*>(eidx)[e1];
            t1 = (int)reinterpret_cast<const long long*>(eidx)[E_EDGES + e1];
        } else {
            s0 = reinterpret_cast<const int*>(eidx)[e0];
            t0 = reinterpret_cast<const int*>(eidx)[E_EDGES + e0];
            s1 = reinterpret_cast<const int*>(eidx)[e1];
            t1 = reinterpret_cast<const int*>(eidx)[E_EDGES + e1];
        }
        const float* Ps0 = g_Ps + (long long)s0 * MSG;
        const float* Pt0 = g_Pt + (long long)t0 * MSG;
        const float* Ps1 = g_Ps + (long long)s1 * MSG;
        const float* Pt1 = g_Pt + (long long)t1 * MSG;

        // ---- GEMM1 + fused epilogue1, 16 n-tiles of 8 cols ----
        int r0s = m * 16 + grp;          // H1 row
        int r1s = r0s + 8;
#pragma unroll 4
        for (int nt2 = 0; nt2 < 16; nt2++) {
            int n0 = hh * 128 + nt2 * 8;
            int col0 = n0 + 2 * quad;
            // gather (independent of MMA; issued early)
            float2 ps0 = *reinterpret_cast<const float2*>(Ps0 + col0);
            float2 pt0 = *reinterpret_cast<const float2*>(Pt0 + col0);
            float2 ps1 = *reinterpret_cast<const float2*>(Ps1 + col0);
            float2 pt1 = *reinterpret_cast<const float2*>(Pt1 + col0);
            // B frags: merged ldx4 over j-pairs; regs map to [2j2][0..1],[2j2+1][0..1]
            unsigned bh[2][4], bl[2][4];
            int bn = n0 + (li & 7);
#pragma unroll
            for (int j2 = 0; j2 < 2; j2++) {
                int c = 4 * j2 + (li >> 3);
                unsigned off = (unsigned)(bn * 128 + ((c ^ (bn & 7)) << 4));
                ldx4(bh[j2], sb + W1H_OFF + off);
                ldx4(bl[j2], sb + W1L_OFF + off);
            }
            float acc[4] = {0.f, 0.f, 0.f, 0.f};
#pragma unroll
            for (int j = 0; j < 4; j++) mma16816(acc, ah[j], &bh[j >> 1][(j & 1) * 2]);
#pragma unroll
            for (int j = 0; j < 4; j++) mma16816(acc, ah[j], &bl[j >> 1][(j & 1) * 2]);
#pragma unroll
            for (int j = 0; j < 4; j++) mma16816(acc, al[j], &bh[j >> 1][(j & 1) * 2]);

            float v0 = lrelu(acc[0] + ps0.x + pt0.x);
            float v1 = lrelu(acc[1] + ps0.y + pt0.y);
            float v2 = lrelu(acc[2] + ps1.x + pt1.x);
            float v3 = lrelu(acc[3] + ps1.y + pt1.y);

            unsigned hpA = bfpack(v1, v0);
            unsigned hpB = bfpack(v3, v2);
            float hv0 = __uint_as_float(hpA << 16), hv1 = __uint_as_float(hpA & 0xffff0000u);
            float hv2 = __uint_as_float(hpB << 16), hv3 = __uint_as_float(hpB & 0xffff0000u);
            unsigned lpA = bfpack(v1 - hv1, v0 - hv0);
            unsigned lpB = bfpack(v3 - hv3, v2 - hv2);

            int cu = (n0 + 2 * quad) >> 3;             // 16B unit = column/8
            int ci = (2 * quad) & 7;
            unsigned offA = (unsigned)(r0s * 512 + ((cu ^ (r0s & 7)) << 4) + ci * 2);
            unsigned offB = (unsigned)(r1s * 512 + ((cu ^ (r1s & 7)) << 4) + ci * 2);
            *reinterpret_cast<unsigned*>(smc + H1H_OFF + offA) = hpA;
            *reinterpret_cast<unsigned*>(smc + H1L_OFF + offA) = lpA;
            *reinterpret_cast<unsigned*>(smc + H1H_OFF + offB) = hpB;
            *reinterpret_cast<unsigned*>(smc + H1L_OFF + offB) = lpB;
        }
        __syncthreads();                 // H1 complete

        // ---- GEMM2 (warps 0-3): D2[64,64] = H1 @ W2T^T ----
        // Loads batched per kf (MLP ~10) with n-pair-merged ldx4 B-frags.
        if (wid < 4) {
            float acc2[8][4];
#pragma unroll
            for (int n = 0; n < 8; n++)
#pragma unroll
                for (int q = 0; q < 4; q++) acc2[n][q] = 0.f;

            int ar = wid * 16 + (li & 15);
            int g = li >> 3;                         // ldx4 lane group 0..3
            int rb = (g >> 1) * 8 + (li & 7);        // row within n-pair
            for (int kf = 0; kf < 16; kf++) {
                // batch all loads first
                unsigned a2h[4], a2l[4];
                int ca = 2 * kf + (li >> 4);
                unsigned offa = (unsigned)(ar * 512 + ((ca ^ (ar & 7)) << 4));
                ldx4(a2h, sb + H1H_OFF + offa);
                ldx4(a2l, sb + H1L_OFF + offa);

                unsigned b2h[4][4], b2l[4][4];
                int cb = 2 * kf + (g & 1);
#pragma unroll
                for (int n2 = 0; n2 < 4; n2++) {
                    int bn = n2 * 16 + rb;           // rows 2*n2 / 2*n2+1 blocks
                    unsigned offb = (unsigned)(bn * 512 + ((cb ^ (bn & 7)) << 4));
                    ldx4(b2h[n2], sb + W2H_OFF + offb);
                    ldx4(b2l[n2], sb + W2L_OFF + offb);
                }
                // then all MMAs
#pragma unroll
                for (int n2 = 0; n2 < 4; n2++) {
                    mma16816(acc2[2 * n2],     a2h, &b2h[n2][0]);
                    mma16816(acc2[2 * n2],     a2h, &b2l[n2][0]);
                    mma16816(acc2[2 * n2],     a2l, &b2h[n2][0]);
                    mma16816(acc2[2 * n2 + 1], a2h, &b2h[n2][2]);
                    mma16816(acc2[2 * n2 + 1], a2h, &b2l[n2][2]);
                    mma16816(acc2[2 * n2 + 1], a2l, &b2h[n2][2]);
                }
            }

            // ---- epilogue2: +b2, RMSNorm, *gamma, store ----
            const float* b2s = reinterpret_cast<const float*>(smc + B2_OFF);
            const float* gms = reinterpret_cast<const float*>(smc + GM_OFF);
            long long ee0 = (long long)tile * 64 + wid * 16 + grp;
            long long ee1 = ee0 + 8;
            float v0[16], v1[16], ssq0 = 0.f, ssq1 = 0.f;
#pragma unroll
            for (int n = 0; n < 8; n++) {
                int col = n * 8 + 2 * quad;
                float ba = b2s[col], bb = b2s[col + 1];
                float a0 = acc2[n][0] + ba, a1 = acc2[n][1] + bb;
                float a2 = acc2[n][2] + ba, a3 = acc2[n][3] + bb;
                v0[n * 2] = a0; v0[n * 2 + 1] = a1;
                v1[n * 2] = a2; v1[n * 2 + 1] = a3;
                ssq0 += a0 * a0 + a1 * a1;
                ssq1 += a2 * a2 + a3 * a3;
            }
            ssq0 += __shfl_xor_sync(0xffffffffu, ssq0, 1);
            ssq0 += __shfl_xor_sync(0xffffffffu, ssq0, 2);
            ssq1 += __shfl_xor_sync(0xffffffffu, ssq1, 1);
            ssq1 += __shfl_xor_sync(0xffffffffu, ssq1, 2);
            float sc0 = rsqrtf(ssq0 * (1.0f / 64.0f) + 1.1920929e-07f);
            float sc1 = rsqrtf(ssq1 * (1.0f / 64.0f) + 1.1920929e-07f);
            float* o0 = out + ee0 * DIM;
            float* o1 = out + ee1 * DIM;
#pragma unroll
            for (int n = 0; n < 8; n++) {
                int col = n * 8 + 2 * quad;
                float ga = gms[col], gb = gms[col + 1];
                *reinterpret_cast<float2*>(o0 + col) =
                    make_float2(v0[n * 2] * sc0 * ga, v0[n * 2 + 1] * sc0 * gb);
                *reinterpret_cast<float2*>(o1 + col) =
                    make_float2(v1[n * 2] * sc1 * ga, v1[n * 2 + 1] * sc1 * gb);
            }
        }
        __syncthreads();                 // H1 free for next tile
    }
}

// ---------------- launch ----------------------------------------------------
extern "C" void kernel_launch(void* const* d_in, const int* in_sizes, int n_in,
                              void* d_out, int out_size) {
    (void)in_sizes; (void)n_in; (void)out_size;
    const float* x_s   = (const float*)d_in[0];
    const float* x_t   = (const float*)d_in[1];
    const void*  eidx  = d_in[2];
    const float* ea    = (const float*)d_in[3];
    const float* xu    = (const float*)d_in[4];
    const float* W1    = (const float*)d_in[5];
    const float* b1    = (const float*)d_in[6];
    const float* W2    = (const float*)d_in[7];
    const float* b2    = (const float*)d_in[8];
    const float* gamma = (const float*)d_in[9];
    float* out = (float*)d_out;

    const int SMEM_PRE = (16384 + 64 * 68) * 4;   // 82944 B

    cudaFuncSetAttribute(node_pre_kernel, cudaFuncAttributeMaxDynamicSharedMemorySize, SMEM_PRE);
    cudaFuncSetAttribute(edge_mma_kernel, cudaFuncAttributeMaxDynamicSharedMemorySize, SMEM_EDGE);

    int nsm = 148;
    cudaDeviceGetAttribute(&nsm, cudaDevAttrMultiProcessorCount, 0);

    detect_idx_kernel<<<1, 32>>>((const unsigned*)eidx);
    cvec_kernel<<<1, MSG>>>(W1, b1, xu);
    split_ea_kernel<<<(E_EDGES * DIM / 4) / 256, 256>>>(ea);
    split_w_kernel<<<64, 256>>>(W1, W2);

    int pgrid = (N_NODES + 63) / 64;
    node_pre_kernel<<<pgrid, 256, SMEM_PRE>>>(x_s, W1,            0, N_NODES);
    node_pre_kernel<<<pgrid, 256, SMEM_PRE>>>(x_t, W1 + 64 * 256, 1, N_NODES);

    edge_mma_kernel<<<nsm, 256, SMEM_EDGE>>>(eidx, b2, gamma, out);
}

// round 17
// speedup vs baseline: 1.4372x; 1.0884x over previous
#include <cuda_runtime.h>
#include <cuda_bf16.h>

#define E_EDGES 1000000
#define N_NODES 50000
#define DIM     64
#define MSG     256
#define TILE_M  64
#define NT      (E_EDGES / TILE_M)      // 15625, exact

// ---------------- device-global scratch (no allocations) -------------------
__device__ __align__(16) float g_Ps[N_NODES * MSG];   // x_s@W1[0:64] + c
__device__ __align__(16) float g_Pt[N_NODES * MSG];   // x_t@W1[64:128]
__device__ __align__(16) float g_c[MSG];
__device__ int g_idx64;

__device__ __align__(16) __nv_bfloat16 g_ea_hi[E_EDGES * DIM];
__device__ __align__(16) __nv_bfloat16 g_ea_lo[E_EDGES * DIM];
__device__ __align__(16) __nv_bfloat16 g_W1T_hi[MSG * DIM];   // [256 n][64 k]
__device__ __align__(16) __nv_bfloat16 g_W1T_lo[MSG * DIM];
__device__ __align__(16) __nv_bfloat16 g_W2T_hi[DIM * MSG];   // [64 n][256 k]
__device__ __align__(16) __nv_bfloat16 g_W2T_lo[DIM * MSG];

// ---------------- helpers ---------------------------------------------------
__device__ __forceinline__ float2 ffma2(float2 a, float2 b, float2 c) {
    float2 d;
    asm("fma.rn.f32x2 %0, %1, %2, %3;"
        : "=l"(reinterpret_cast<unsigned long long &>(d))
        : "l"(reinterpret_cast<unsigned long long &>(a)),
          "l"(reinterpret_cast<unsigned long long &>(b)),
          "l"(reinterpret_cast<unsigned long long &>(c)));
    return d;
}
__device__ __forceinline__ float lrelu(float v) { return v >= 0.0f ? v : 0.01f * v; }

// pack: hi halfword = bf16(hv), lo halfword = bf16(lv)
__device__ __forceinline__ unsigned bfpack(float hv, float lv) {
    unsigned r;
    asm("cvt.rn.bf16x2.f32 %0, %1, %2;" : "=r"(r) : "f"(hv), "f"(lv));
    return r;
}
__device__ __forceinline__ void cp16(unsigned sa, const void* g) {
    asm volatile("cp.async.ca.shared.global [%0], [%1], 16;" :: "r"(sa), "l"(g));
}
__device__ __forceinline__ void cp_commit()  { asm volatile("cp.async.commit_group;"); }
__device__ __forceinline__ void cp_wait_all(){ asm volatile("cp.async.wait_group 0;"); }

__device__ __forceinline__ void ldx4(unsigned* r, unsigned a) {
    asm volatile("ldmatrix.sync.aligned.m8n8.x4.shared.b16 {%0,%1,%2,%3}, [%4];"
                 : "=r"(r[0]), "=r"(r[1]), "=r"(r[2]), "=r"(r[3]) : "r"(a));
}
__device__ __forceinline__ void mma16816(float* c, const unsigned* a, const unsigned* b) {
    asm volatile("mma.sync.aligned.m16n8k16.row.col.f32.bf16.bf16.f32 "
                 "{%0,%1,%2,%3}, {%4,%5,%6,%7}, {%8,%9}, {%0,%1,%2,%3};"
                 : "+f"(c[0]), "+f"(c[1]), "+f"(c[2]), "+f"(c[3])
                 : "r"(a[0]), "r"(a[1]), "r"(a[2]), "r"(a[3]), "r"(b[0]), "r"(b[1]));
}

// ---------------- prologue kernels ------------------------------------------
__global__ void detect_idx_kernel(const unsigned* __restrict__ idx) {
    if (threadIdx.x == 0) {
        int is64 = 1;
        for (int i = 0; i < 64; i++)
            if (idx[2 * i + 1] != 0u) { is64 = 0; break; }
        g_idx64 = is64;
    }
}

__global__ void cvec_kernel(const float* __restrict__ W1, const float* __restrict__ b1,
                            const float* __restrict__ xu) {
    int j = threadIdx.x;
    float acc = b1[j];
#pragma unroll 8
    for (int k = 0; k < DIM; k++) acc = fmaf(xu[k], W1[(192 + k) * MSG + j], acc);
    g_c[j] = acc;
}

__global__ __launch_bounds__(256) void split_ea_kernel(const float* __restrict__ ea) {
    long long i = (long long)blockIdx.x * 256 + threadIdx.x;   // float4 id
    float4 x = reinterpret_cast<const float4*>(ea)[i];
    unsigned hp0 = bfpack(x.y, x.x), hp1 = bfpack(x.w, x.z);
    float h0 = __uint_as_float(hp0 << 16), h1 = __uint_as_float(hp0 & 0xffff0000u);
    float h2 = __uint_as_float(hp1 << 16), h3 = __uint_as_float(hp1 & 0xffff0000u);
    unsigned lp0 = bfpack(x.y - h1, x.x - h0), lp1 = bfpack(x.w - h3, x.z - h2);
    reinterpret_cast<uint2*>(g_ea_hi)[i] = make_uint2(hp0, hp1);
    reinterpret_cast<uint2*>(g_ea_lo)[i] = make_uint2(lp0, lp1);
}

__global__ void split_w_kernel(const float* __restrict__ W1, const float* __restrict__ W2) {
    int i = blockIdx.x * 256 + threadIdx.x;   // 0..16383
    {   // W1T[n][k] = W1[(128+k)*256+n]
        int n = i >> 6, k = i & 63;
        float x = W1[(128 + k) * MSG + n];
        __nv_bfloat16 h = __float2bfloat16(x);
        g_W1T_hi[i] = h;
        g_W1T_lo[i] = __float2bfloat16(x - __bfloat162float(h));
    }
    {   // W2T[n][k] = W2[k*64+n]
        int n = i >> 8, k = i & 255;
        float x = W2[k * DIM + n];
        __nv_bfloat16 h = __float2bfloat16(x);
        g_W2T_hi[i] = h;
        g_W2T_lo[i] = __float2bfloat16(x - __bfloat162float(h));
    }
}

// ---------------- node precompute (fp32; c folded into Ps) ------------------
__global__ __launch_bounds__(256, 1)
void node_pre_kernel(const float* __restrict__ X, const float* __restrict__ Wsub,
                     int which, int N) {
    extern __shared__ float sm[];
    float* sW = sm;
    float* sA = sm + 16384;
    float* P  = which ? g_Pt : g_Ps;

    int t = threadIdx.x;
    int row0 = blockIdx.x * 64;
#pragma unroll
    for (int i = 0; i < 16; i++) {
        int idx = t + i * 256;
        reinterpret_cast<float4*>(sW)[idx] = reinterpret_cast<const float4*>(Wsub)[idx];
    }
#pragma unroll
    for (int i = 0; i < 4; i++) {
        int f = t + i * 256;
        int r = f >> 4, q = f & 15;
        float4 v = make_float4(0.f, 0.f, 0.f, 0.f);
        if (row0 + r < N) v = reinterpret_cast<const float4*>(X)[(row0 + r) * 16 + q];
        *reinterpret_cast<float4*>(&sA[r * 68 + q * 4]) = v;
    }
    __syncthreads();

    int tx = t & 31, ty = t >> 5;
    float2 acc[8][4];
#pragma unroll
    for (int e = 0; e < 8; e++)
#pragma unroll
        for (int j = 0; j < 4; j++) acc[e][j] = make_float2(0.f, 0.f);

    for (int k4 = 0; k4 < 64; k4 += 4) {
        float4 a[8];
#pragma unroll
        for (int e = 0; e < 8; e++)
            a[e] = *reinterpret_cast<const float4*>(&sA[(ty * 8 + e) * 68 + k4]);
#pragma unroll
        for (int kk = 0; kk < 4; kk++) {
            float4 b0 = *reinterpret_cast<const float4*>(&sW[(k4 + kk) * 256 + tx * 4]);
            float4 b1 = *reinterpret_cast<const float4*>(&sW[(k4 + kk) * 256 + 128 + tx * 4]);
#pragma unroll
            for (int e = 0; e < 8; e++) {
                float av = (kk == 0) ? a[e].x : (kk == 1) ? a[e].y : (kk == 2) ? a[e].z : a[e].w;
                float2 ad = make_float2(av, av);
                acc[e][0] = ffma2(ad, make_float2(b0.x, b0.y), acc[e][0]);
                acc[e][1] = ffma2(ad, make_float2(b0.z, b0.w), acc[e][1]);
                acc[e][2] = ffma2(ad, make_float2(b1.x, b1.y), acc[e][2]);
                acc[e][3] = ffma2(ad, make_float2(b1.z, b1.w), acc[e][3]);
            }
        }
    }

    float4 c0 = make_float4(0.f, 0.f, 0.f, 0.f), c1 = c0;
    if (which == 0) {
        c0 = *reinterpret_cast<const float4*>(&g_c[tx * 4]);
        c1 = *reinterpret_cast<const float4*>(&g_c[128 + tx * 4]);
    }
#pragma unroll
    for (int e = 0; e < 8; e++) {
        int r = row0 + ty * 8 + e;
        if (r < N) {
            float4 o0 = make_float4(acc[e][0].x + c0.x, acc[e][0].y + c0.y,
                                    acc[e][1].x + c0.z, acc[e][1].y + c0.w);
            float4 o1 = make_float4(acc[e][2].x + c1.x, acc[e][2].y + c1.y,
                                    acc[e][3].x + c1.z, acc[e][3].y + c1.w);
            *reinterpret_cast<float4*>(&P[r * 256 + tx * 4])       = o0;
            *reinterpret_cast<float4*>(&P[r * 256 + 128 + tx * 4]) = o1;
        }
    }
}

// ---------------- HMMA edge kernel ------------------------------------------
// smem map (bytes). 16B-unit XOR swizzle: unit c -> c ^ (row & 7)
#define W1H_OFF 0          // 256 rows x 128B
#define W1L_OFF 32768
#define W2H_OFF 65536      // 64 rows x 512B
#define W2L_OFF 98304
#define H1H_OFF 131072     // 64 rows x 512B
#define H1L_OFF 163840
#define EA_OFF  196608     // 2 bufs x (hi 8KB + lo 8KB)
#define B2_OFF  229376     // 64 f32
#define GM_OFF  229632     // 64 f32
#define SMEM_EDGE 229888

__global__ __launch_bounds__(256, 1)
void edge_mma_kernel(const void* __restrict__ eidx, const float* __restrict__ b2,
                     const float* __restrict__ gamma, float* __restrict__ out) {
    extern __shared__ char smc[];
    unsigned sb = (unsigned)__cvta_generic_to_shared(smc);
    int t = threadIdx.x, wid = t >> 5, li = t & 31;

    // ---- one-time: weights (swizzled), b2/gamma ----
    for (int i = t; i < 2048; i += 256) {           // W1T: 256x8 units
        int r = i >> 3, c = i & 7;
        unsigned off = (unsigned)(r * 128 + ((c ^ (r & 7)) << 4));
        *reinterpret_cast<float4*>(smc + W1H_OFF + off) = reinterpret_cast<const float4*>(g_W1T_hi)[i];
        *reinterpret_cast<float4*>(smc + W1L_OFF + off) = reinterpret_cast<const float4*>(g_W1T_lo)[i];
    }
    for (int i = t; i < 2048; i += 256) {           // W2T: 64x32 units
        int r = i >> 5, c = i & 31;
        unsigned off = (unsigned)(r * 512 + ((c ^ (r & 7)) << 4));
        *reinterpret_cast<float4*>(smc + W2H_OFF + off) = reinterpret_cast<const float4*>(g_W2T_hi)[i];
        *reinterpret_cast<float4*>(smc + W2L_OFF + off) = reinterpret_cast<const float4*>(g_W2T_lo)[i];
    }
    if (t < 16)      reinterpret_cast<float4*>(smc + B2_OFF)[t]      = reinterpret_cast<const float4*>(b2)[t];
    else if (t < 32) reinterpret_cast<float4*>(smc + GM_OFF)[t - 16] = reinterpret_cast<const float4*>(gamma)[t - 16];
    int idx64 = g_idx64;

    // ---- prefetch first EA tile into buf 0 ----
    int tile = blockIdx.x;
    {
#pragma unroll
        for (int i = 0; i < 2; i++) {
            int u = t + i * 256;
            int r = u >> 3, c = u & 7;
            unsigned off = (unsigned)(r * 128 + ((c ^ (r & 7)) << 4));
            cp16(sb + EA_OFF + off,        (const char*)g_ea_hi + ((long long)tile * 64 + r) * 128 + c * 16);
            cp16(sb + EA_OFF + 8192 + off, (const char*)g_ea_lo + ((long long)tile * 64 + r) * 128 + c * 16);
        }
    }
    cp_commit();

    int m = wid & 3, hh = wid >> 2;      // GEMM1 role
    int grp = li >> 2, quad = li & 3;
    int buf = 0;

    for (; tile < NT; tile += gridDim.x) {
        unsigned eaH = sb + EA_OFF + buf * 16384;
        unsigned eaL = eaH + 8192;

        cp_wait_all();
        __syncthreads();                 // EA[buf] ready; H1 free; EA[buf^1] readers done

        // ---- immediately stream next tile into the other buffer ----
        {
            int nt_ = tile + gridDim.x;
            if (nt_ < NT) {
                unsigned nH = sb + EA_OFF + (buf ^ 1) * 16384;
#pragma unroll
                for (int i = 0; i < 2; i++) {
                    int u = t + i * 256;
                    int r = u >> 3, c = u & 7;
                    unsigned off = (unsigned)(r * 128 + ((c ^ (r & 7)) << 4));
                    cp16(nH + off,        (const char*)g_ea_hi + ((long long)nt_ * 64 + r) * 128 + c * 16);
                    cp16(nH + 8192 + off, (const char*)g_ea_lo + ((long long)nt_ * 64 + r) * 128 + c * 16);
                }
            }
            cp_commit();
        }

        // ---- A-frags (EA) into regs ----
        unsigned ah[4][4], al[4][4];
        {
            int ar = m * 16 + (li & 15);
#pragma unroll
            for (int j = 0; j < 4; j++) {
                int c = 2 * j + (li >> 4);
                unsigned off = (unsigned)(ar * 128 + ((c ^ (ar & 7)) << 4));
                ldx4(ah[j], eaH + off);
                ldx4(al[j], eaL + off);
            }
        }

        // ---- edge indices for this thread's two rows ----
        long long e0 = (long long)tile * 64 + m * 16 + grp;   // row grp
        long long e1 = e0 + 8;                                // row grp+8
        int s0, t0, s1, t1;
        if (idx64) {
            s0 = (int)reinterpret_cast<const long long*>(eidx)[e0];
            t0 = (int)reinterpret_cast<const long long*>(eidx)[E_EDGES + e0];
            s1 = (int)reinterpret_cast<const long long*>(eidx)[e1];
            t1 = (int)reinterpret_cast<const long long*>(eidx)[E_EDGES + e1];
        } else {
            s0 = reinterpret_cast<const int*>(eidx)[e0];
            t0 = reinterpret_cast<const int*>(eidx)[E_EDGES + e0];
            s1 = reinterpret_cast<const int*>(eidx)[e1];
            t1 = reinterpret_cast<const int*>(eidx)[E_EDGES + e1];
        }
        const float* Ps0 = g_Ps + (long long)s0 * MSG;
        const float* Pt0 = g_Pt + (long long)t0 * MSG;
        const float* Ps1 = g_Ps + (long long)s1 * MSG;
        const float* Pt1 = g_Pt + (long long)t1 * MSG;

        // ---- GEMM1 + fused epilogue1, 16 n-tiles of 8 cols ----
        int r0s = m * 16 + grp;          // H1 row
        int r1s = r0s + 8;
#pragma unroll 4
        for (int nt2 = 0; nt2 < 16; nt2++) {
            int n0 = hh * 128 + nt2 * 8;
            int col0 = n0 + 2 * quad;
            // gather (independent of MMA; issued early)
            float2 ps0 = *reinterpret_cast<const float2*>(Ps0 + col0);
            float2 pt0 = *reinterpret_cast<const float2*>(Pt0 + col0);
            float2 ps1 = *reinterpret_cast<const float2*>(Ps1 + col0);
            float2 pt1 = *reinterpret_cast<const float2*>(Pt1 + col0);
            // B frags: merged ldx4 over j-pairs
            unsigned bh[2][4], bl[2][4];
            int bn = n0 + (li & 7);
#pragma unroll
            for (int j2 = 0; j2 < 2; j2++) {
                int c = 4 * j2 + (li >> 3);
                unsigned off = (unsigned)(bn * 128 + ((c ^ (bn & 7)) << 4));
                ldx4(bh[j2], sb + W1H_OFF + off);
                ldx4(bl[j2], sb + W1L_OFF + off);
            }
            // three INDEPENDENT accumulator chains (break the 12-deep RAW chain)
            float accA[4] = {0.f, 0.f, 0.f, 0.f};
            float accB[4] = {0.f, 0.f, 0.f, 0.f};
            float accC[4] = {0.f, 0.f, 0.f, 0.f};
#pragma unroll
            for (int j = 0; j < 4; j++) {
                mma16816(accA, ah[j], &bh[j >> 1][(j & 1) * 2]);
                mma16816(accB, ah[j], &bl[j >> 1][(j & 1) * 2]);
                mma16816(accC, al[j], &bh[j >> 1][(j & 1) * 2]);
            }

            float v0 = lrelu(accA[0] + accB[0] + accC[0] + ps0.x + pt0.x);
            float v1 = lrelu(accA[1] + accB[1] + accC[1] + ps0.y + pt0.y);
            float v2 = lrelu(accA[2] + accB[2] + accC[2] + ps1.x + pt1.x);
            float v3 = lrelu(accA[3] + accB[3] + accC[3] + ps1.y + pt1.y);

            unsigned hpA = bfpack(v1, v0);
            unsigned hpB = bfpack(v3, v2);
            float hv0 = __uint_as_float(hpA << 16), hv1 = __uint_as_float(hpA & 0xffff0000u);
            float hv2 = __uint_as_float(hpB << 16), hv3 = __uint_as_float(hpB & 0xffff0000u);
            unsigned lpA = bfpack(v1 - hv1, v0 - hv0);
            unsigned lpB = bfpack(v3 - hv3, v2 - hv2);

            int cu = (n0 + 2 * quad) >> 3;             // 16B unit = column/8
            int ci = (2 * quad) & 7;
            unsigned offA = (unsigned)(r0s * 512 + ((cu ^ (r0s & 7)) << 4) + ci * 2);
            unsigned offB = (unsigned)(r1s * 512 + ((cu ^ (r1s & 7)) << 4) + ci * 2);
            *reinterpret_cast<unsigned*>(smc + H1H_OFF + offA) = hpA;
            *reinterpret_cast<unsigned*>(smc + H1L_OFF + offA) = lpA;
            *reinterpret_cast<unsigned*>(smc + H1H_OFF + offB) = hpB;
            *reinterpret_cast<unsigned*>(smc + H1L_OFF + offB) = lpB;
        }
        __syncthreads();                 // H1 complete

        // ---- GEMM2 (warps 0-3): D2[64,64] = H1 @ W2T^T ----
        if (wid < 4) {
            float acc2[8][4];
#pragma unroll
            for (int n = 0; n < 8; n++)
#pragma unroll
                for (int q = 0; q < 4; q++) acc2[n][q] = 0.f;

            int ar = wid * 16 + (li & 15);
            int g = li >> 3;                         // ldx4 lane group 0..3
            int rb = (g >> 1) * 8 + (li & 7);        // row within n-pair
            for (int kf = 0; kf < 16; kf++) {
                // batch all loads first
                unsigned a2h[4], a2l[4];
                int ca = 2 * kf + (li >> 4);
                unsigned offa = (unsigned)(ar * 512 + ((ca ^ (ar & 7)) << 4));
                ldx4(a2h, sb + H1H_OFF + offa);
                ldx4(a2l, sb + H1L_OFF + offa);

                unsigned b2h[4][4], b2l[4][4];
                int cb = 2 * kf + (g & 1);
#pragma unroll
                for (int n2 = 0; n2 < 4; n2++) {
                    int bn = n2 * 16 + rb;
                    unsigned offb = (unsigned)(bn * 512 + ((cb ^ (bn & 7)) << 4));
                    ldx4(b2h[n2], sb + W2H_OFF + offb);
                    ldx4(b2l[n2], sb + W2L_OFF + offb);
                }
                // then all MMAs (8 independent acc chains)
#pragma unroll
                for (int n2 = 0; n2 < 4; n2++) {
                    mma16816(acc2[2 * n2],     a2h, &b2h[n2][0]);
                    mma16816(acc2[2 * n2],     a2h, &b2l[n2][0]);
                    mma16816(acc2[2 * n2],     a2l, &b2h[n2][0]);
                    mma16816(acc2[2 * n2 + 1], a2h, &b2h[n2][2]);
                    mma16816(acc2[2 * n2 + 1], a2h, &b2l[n2][2]);
                    mma16816(acc2[2 * n2 + 1], a2l, &b2h[n2][2]);
                }
            }

            // ---- epilogue2: +b2, RMSNorm, *gamma, store ----
            const float* b2s = reinterpret_cast<const float*>(smc + B2_OFF);
            const float* gms = reinterpret_cast<const float*>(smc + GM_OFF);
            long long ee0 = (long long)tile * 64 + wid * 16 + grp;
            long long ee1 = ee0 + 8;
            float v0[16], v1[16], ssq0 = 0.f, ssq1 = 0.f;
#pragma unroll
            for (int n = 0; n < 8; n++) {
                int col = n * 8 + 2 * quad;
                float ba = b2s[col], bb = b2s[col + 1];
                float a0 = acc2[n][0] + ba, a1 = acc2[n][1] + bb;
                float a2 = acc2[n][2] + ba, a3 = acc2[n][3] + bb;
                v0[n * 2] = a0; v0[n * 2 + 1] = a1;
                v1[n * 2] = a2; v1[n * 2 + 1] = a3;
                ssq0 += a0 * a0 + a1 * a1;
                ssq1 += a2 * a2 + a3 * a3;
            }
            ssq0 += __shfl_xor_sync(0xffffffffu, ssq0, 1);
            ssq0 += __shfl_xor_sync(0xffffffffu, ssq0, 2);
            ssq1 += __shfl_xor_sync(0xffffffffu, ssq1, 1);
            ssq1 += __shfl_xor_sync(0xffffffffu, ssq1, 2);
            float sc0 = rsqrtf(ssq0 * (1.0f / 64.0f) + 1.1920929e-07f);
            float sc1 = rsqrtf(ssq1 * (1.0f / 64.0f) + 1.1920929e-07f);
            float* o0 = out + ee0 * DIM;
            float* o1 = out + ee1 * DIM;
#pragma unroll
            for (int n = 0; n < 8; n++) {
                int col = n * 8 + 2 * quad;
                float ga = gms[col], gb = gms[col + 1];
                *reinterpret_cast<float2*>(o0 + col) =
                    make_float2(v0[n * 2] * sc0 * ga, v0[n * 2 + 1] * sc0 * gb);
                *reinterpret_cast<float2*>(o1 + col) =
                    make_float2(v1[n * 2] * sc1 * ga, v1[n * 2 + 1] * sc1 * gb);
            }
        }
        __syncthreads();                 // H1 free for next tile
        buf ^= 1;
    }
}

// ---------------- launch ----------------------------------------------------
extern "C" void kernel_launch(void* const* d_in, const int* in_sizes, int n_in,
                              void* d_out, int out_size) {
    (void)in_sizes; (void)n_in; (void)out_size;
    const float* x_s   = (const float*)d_in[0];
    const float* x_t   = (const float*)d_in[1];
    const void*  eidx  = d_in[2];
    const float* ea    = (const float*)d_in[3];
    const float* xu    = (const float*)d_in[4];
    const float* W1    = (const float*)d_in[5];
    const float* b1    = (const float*)d_in[6];
    const float* W2    = (const float*)d_in[7];
    const float* b2    = (const float*)d_in[8];
    const float* gamma = (const float*)d_in[9];
    float* out = (float*)d_out;

    const int SMEM_PRE = (16384 + 64 * 68) * 4;   // 82944 B

    cudaFuncSetAttribute(node_pre_kernel, cudaFuncAttributeMaxDynamicSharedMemorySize, SMEM_PRE);
    cudaFuncSetAttribute(edge_mma_kernel, cudaFuncAttributeMaxDynamicSharedMemorySize, SMEM_EDGE);

    int nsm = 148;
    cudaDeviceGetAttribute(&nsm, cudaDevAttrMultiProcessorCount, 0);

    detect_idx_kernel<<<1, 32>>>((const unsigned*)eidx);
    cvec_kernel<<<1, MSG>>>(W1, b1, xu);
    split_ea_kernel<<<(E_EDGES * DIM / 4) / 256, 256>>>(ea);
    split_w_kernel<<<64, 256>>>(W1, W2);

    int pgrid = (N_NODES + 63) / 64;
    node_pre_kernel<<<pgrid, 256, SMEM_PRE>>>(x_s, W1,            0, N_NODES);
    node_pre_kernel<<<pgrid, 256, SMEM_PRE>>>(x_t, W1 + 64 * 256, 1, N_NODES);

    edge_mma_kernel<<<nsm, 256, SMEM_EDGE>>>(eidx, b2, gamma, out);
}